// round 16
// baseline (speedup 1.0000x reference)
#include <cuda_runtime.h>
#include <math.h>
#include <stdint.h>

// ---------------------------------------------------------------------------
// Problem constants
// ---------------------------------------------------------------------------
#define BATCH 32
#define IMG   224
#define PATCH 16
#define DM    768
#define NH    12
#define HS    64
#define NL    12
#define TB    32
#define MLPD  3072
#define AOUT  7
#define NPATCH 196
#define SEQ   426
#define SEQT  448               // padded t-stride for transposed V
#define TOK   (BATCH*SEQ)       // 13632
#define SCALE 0.03608439182435161f  // 768^-0.5

// ---------------------------------------------------------------------------
// Scratch.  u32 buffers hold tf32-bit values.
// ---------------------------------------------------------------------------
__device__ float    g_X  [TOK*DM];
__device__ uint32_t g_XN [TOK*DM];
__device__ uint32_t g_Q  [TOK*DM];
__device__ uint32_t g_K  [TOK*DM];
__device__ uint32_t g_V  [TOK*DM];
__device__ uint32_t g_VT [BATCH*NH*HS*SEQT];   // V transposed: [(b,h), d, t]
__device__ uint32_t g_ATT[TOK*DM];
__device__ uint32_t g_H  [TOK*MLPD];
__device__ uint32_t g_P  [BATCH*NPATCH*DM];
__device__ uint32_t g_CLS[BATCH*DM];
__device__ uint32_t g_HID[BATCH*4*DM];

// Pre-swizzled weights (tf32 bits, smem-tile order), fixed offsets
#define OFF_PATCH 0LL
#define SZ_PATCH  (589824LL)
#define OFF_WQ    (OFF_PATCH + SZ_PATCH)
#define SZ_WQKV   (12LL*589824)
#define OFF_WK    (OFF_WQ + SZ_WQKV)
#define OFF_WV    (OFF_WK + SZ_WQKV)
#define OFF_WO    (OFF_WV + SZ_WQKV)
#define OFF_W1    (OFF_WO + SZ_WQKV)
#define SZ_WMLP   (12LL*2359296)
#define OFF_W2    (OFF_W1 + SZ_WMLP)
#define OFF_AH1   (OFF_W2 + SZ_WMLP)
#define SZ_AH1    (2359296LL)
#define OFF_AH2   (OFF_AH1 + SZ_AH1)
#define SZ_AH2    (21504LL)
#define WT_TOTAL  (OFF_AH2 + SZ_AH2)
__device__ uint32_t g_WT[WT_TOTAL];

// ---------------------------------------------------------------------------
// Helpers
// ---------------------------------------------------------------------------
__device__ __forceinline__ uint32_t f2tf32(float f) {
    uint32_t r;
    asm("cvt.rna.tf32.f32 %0, %1;" : "=r"(r) : "f"(f));
    return r;
}

__device__ __forceinline__ void mma_tf32(float (&d)[4], const uint32_t (&a)[4],
                                         const uint32_t (&b)[2]) {
    asm volatile(
        "mma.sync.aligned.m16n8k8.row.col.f32.tf32.tf32.f32 "
        "{%0,%1,%2,%3}, {%4,%5,%6,%7}, {%8,%9}, {%0,%1,%2,%3};"
        : "+f"(d[0]), "+f"(d[1]), "+f"(d[2]), "+f"(d[3])
        : "r"(a[0]), "r"(a[1]), "r"(a[2]), "r"(a[3]), "r"(b[0]), "r"(b[1]));
}

__device__ __forceinline__ uint32_t smem_u32(const void* p) {
    uint32_t a;
    asm("{ .reg .u64 t; cvta.to.shared.u64 t, %1; cvt.u32.u64 %0, t; }"
        : "=r"(a) : "l"(p));
    return a;
}

__device__ __forceinline__ void cp16(uint32_t dst, const void* src, int sz) {
    asm volatile("cp.async.cg.shared.global [%0], [%1], 16, %2;"
                 :: "r"(dst), "l"(src), "r"(sz) : "memory");
}
__device__ __forceinline__ void cp_commit() {
    asm volatile("cp.async.commit_group;" ::: "memory");
}
__device__ __forceinline__ void cp_wait1() {
    asm volatile("cp.async.wait_group 1;" ::: "memory");
}
__device__ __forceinline__ void cp_wait0() {
    asm volatile("cp.async.wait_group 0;" ::: "memory");
}

// ---------------------------------------------------------------------------
// Weight swizzle kernels (dst-major, coalesced writes).
// ---------------------------------------------------------------------------
__global__ void swz_normal_k(const float* __restrict__ src, uint32_t* __restrict__ dst,
                             int K, int N, int nLayers)
{
    const int kph = K >> 5;
    long long per = (long long)K * N;
    long long total = per * nLayers;
    long long i = (long long)blockIdx.x * blockDim.x + threadIdx.x;
    long long stride = (long long)gridDim.x * blockDim.x;
    for (; i < total; i += stride) {
        long long l = i / per, r = i % per;
        int blk   = (int)(r >> 12);
        int inner = (int)(r & 4095);
        int nl = inner >> 5, kl = inner & 31;
        int bn = blk / kph, bk = blk % kph;
        int n = bn * 128 + nl, k = bk * 32 + kl;
        dst[i] = f2tf32(src[l * per + (long long)k * N + n]);
    }
}

__global__ void swz_head_k(const float* __restrict__ src, uint32_t* __restrict__ dst,
                           int nLayers)
{
    long long per = 589824LL;
    long long total = per * nLayers;
    long long i = (long long)blockIdx.x * blockDim.x + threadIdx.x;
    long long stride = (long long)gridDim.x * blockDim.x;
    for (; i < total; i += stride) {
        long long l = i / per, r = i % per;
        int blk   = (int)(r >> 12);
        int inner = (int)(r & 4095);
        int nl = inner >> 5, kl = inner & 31;
        int bn = blk / 24, bk = blk % 24;
        int n = bn * 128 + nl, k = bk * 32 + kl;
        dst[i] = f2tf32(src[l * per + (long long)(n >> 6) * (768 * 64) +
                            (long long)k * 64 + (n & 63)]);
    }
}

__global__ void cvt_k(const float* __restrict__ src, uint32_t* __restrict__ dst,
                      long long n)
{
    long long i = (long long)blockIdx.x * blockDim.x + threadIdx.x;
    long long stride = (long long)gridDim.x * blockDim.x;
    for (; i < n; i += stride) dst[i] = f2tf32(src[i]);
}

// ---------------------------------------------------------------------------
// V transpose: Vf[(b,t), h*64+d] -> Vt[(b*NH+h)*64+d][t]  (t-stride SEQT, pad 0)
// grid (7 t-tiles, BATCH*NH), 256 threads; 64x64 smem tile, conflict-free.
// ---------------------------------------------------------------------------
__global__ void __launch_bounds__(256)
vtrans_k(const uint32_t* __restrict__ Vf, uint32_t* __restrict__ Vt)
{
    __shared__ uint32_t sm[64 * 65];
    const int z   = blockIdx.y;
    const int b   = z / NH, h = z % NH;
    const int tt0 = blockIdx.x * 64;
    const int tid = threadIdx.x;

    #pragma unroll
    for (int i = 0; i < 16; i++) {
        int e = tid + i * 256;
        int tl = e >> 6, d = e & 63;
        int t = tt0 + tl;
        uint32_t v = 0u;
        if (t < SEQ)
            v = Vf[((long long)(b * SEQ + t)) * DM + h * HS + d];
        sm[d * 65 + tl] = v;
    }
    __syncthreads();
    #pragma unroll
    for (int i = 0; i < 16; i++) {
        int e = tid + i * 256;
        int dl = e >> 6, tl = e & 63;
        Vt[((long long)z * HS + dl) * SEQT + tt0 + tl] = sm[dl * 65 + tl];
    }
}

// ---------------------------------------------------------------------------
// GEMM core: 128x128 tile, BK=32 per phase, cp.async double-buffered.
// ---------------------------------------------------------------------------
#define ABUF (128 * 36)
#define GSMEM (4 * ABUF * 4)

template<bool RELU, bool BIAS, bool ATOMIC, bool OUTTF>
__device__ __forceinline__ void gemm_core(
    uint32_t* dsm,
    const uint32_t* __restrict__ A, const uint32_t* __restrict__ B,
    float* __restrict__ C, const float* __restrict__ bias,
    int M, int lda, int kphases, int ldc,
    int row0, int col0, int kt0, int kend)
{
    const int tid    = threadIdx.x;
    const int wid    = tid >> 5;
    const int lane   = tid & 31;
    const int g      = lane >> 2;
    const int tg     = lane & 3;
    const int warp_m = (wid & 3) * 32;
    const int warp_n = (wid >> 2) * 64;

    float acc[2][8][4];
    #pragma unroll
    for (int mt = 0; mt < 2; mt++)
        #pragma unroll
        for (int nt = 0; nt < 8; nt++)
            #pragma unroll
            for (int i = 0; i < 4; i++) acc[mt][nt][i] = 0.f;

    const uint32_t smem_base = smem_u32(dsm);

    auto prefetch = [&](int buf, int kt) {
        uint32_t abase = smem_base + (uint32_t)buf * ABUF * 4;
        uint32_t bbase = smem_base + (uint32_t)(2 + buf) * ABUF * 4;
        #pragma unroll
        for (int i = 0; i < 4; i++) {
            int idx = tid + i * 256;
            int r   = idx >> 3;
            int kq  = (idx & 7) * 4;
            int gr  = row0 + r;
            const uint32_t* ap = A + (long long)gr * lda + kt + kq;
            cp16(abase + (uint32_t)(r * 36 + kq) * 4, ap, (gr < M) ? 16 : 0);
        }
        const uint32_t* bp = B +
            ((long long)(col0 >> 7) * kphases + (kt >> 5)) * 4096;
        #pragma unroll
        for (int i = 0; i < 4; i++) {
            int idx4 = (tid + i * 256) * 4;
            int n = idx4 >> 5, w = idx4 & 31;
            cp16(bbase + (uint32_t)(n * 36 + w) * 4, bp + idx4, 16);
        }
    };

    const int ntiles = (kend - kt0) >> 5;
    prefetch(0, kt0);
    cp_commit();

    for (int t = 0; t < ntiles; t++) {
        const int cur = t & 1;
        const bool more = (t + 1 < ntiles);
        if (more) { prefetch(cur ^ 1, kt0 + (t + 1) * 32); cp_commit(); }
        if (more) cp_wait1(); else cp_wait0();
        __syncthreads();

        const uint32_t (*As)[36] = (const uint32_t (*)[36])(dsm + cur * ABUF);
        const uint32_t (*Bs)[36] = (const uint32_t (*)[36])(dsm + (2 + cur) * ABUF);

        #pragma unroll
        for (int kk = 0; kk < 32; kk += 8) {
            uint32_t af[2][4];
            #pragma unroll
            for (int mt = 0; mt < 2; mt++) {
                int rs = warp_m + mt * 16 + g;
                af[mt][0] = As[rs][kk + tg];
                af[mt][1] = As[rs + 8][kk + tg];
                af[mt][2] = As[rs][kk + tg + 4];
                af[mt][3] = As[rs + 8][kk + tg + 4];
            }
            uint32_t bf[8][2];
            #pragma unroll
            for (int nt = 0; nt < 8; nt++) {
                int cs = warp_n + nt * 8 + g;
                bf[nt][0] = Bs[cs][kk + tg];
                bf[nt][1] = Bs[cs][kk + tg + 4];
            }
            #pragma unroll
            for (int mt = 0; mt < 2; mt++)
                #pragma unroll
                for (int nt = 0; nt < 8; nt++)
                    mma_tf32(acc[mt][nt], af[mt], bf[nt]);
        }
        __syncthreads();
    }

    #pragma unroll
    for (int mt = 0; mt < 2; mt++) {
        #pragma unroll
        for (int nt = 0; nt < 8; nt++) {
            int r_base = row0 + warp_m + mt * 16 + g;
            int c_base = col0 + warp_n + nt * 8 + tg * 2;
            #pragma unroll
            for (int h = 0; h < 2; h++) {
                int r = r_base + h * 8;
                if (r >= M) continue;
                #pragma unroll
                for (int j = 0; j < 2; j++) {
                    int c = c_base + j;
                    float v = acc[mt][nt][h * 2 + j];
                    long long ci = (long long)r * ldc + c;
                    if (ATOMIC) {
                        if (BIAS && blockIdx.z == 0) v += bias[c];
                        atomicAdd(&C[ci], v);
                    } else {
                        if (BIAS) v += bias[c];
                        if (RELU) v = fmaxf(v, 0.f);
                        if (OUTTF) ((uint32_t*)C)[ci] = f2tf32(v);
                        else       C[ci] = v;
                    }
                }
            }
        }
    }
}

template<bool RELU, bool BIAS, bool ATOMIC, bool OUTTF>
__global__ void __launch_bounds__(256, 2)
gemm_main(const uint32_t* __restrict__ A, const uint32_t* __restrict__ B,
          float* __restrict__ C, const float* __restrict__ bias,
          int M, int lda, int kphases, int ldc, int ksz)
{
    extern __shared__ uint32_t dsm[];
    int kt0 = blockIdx.z * ksz;
    gemm_core<RELU, BIAS, ATOMIC, OUTTF>(
        dsm, A, B, C, bias, M, lda, kphases, ldc,
        blockIdx.y * 128, blockIdx.x * 128, kt0, kt0 + ksz);
}

__global__ void __launch_bounds__(256, 2)
gemm_qkv(const uint32_t* __restrict__ A,
         const uint32_t* __restrict__ Bq, const uint32_t* __restrict__ Bk,
         const uint32_t* __restrict__ Bv,
         uint32_t* __restrict__ Cq, uint32_t* __restrict__ Ck,
         uint32_t* __restrict__ Cv, int M)
{
    extern __shared__ uint32_t dsm[];
    const int mat  = blockIdx.x / 6;
    const int colt = blockIdx.x % 6;
    const uint32_t* B = (mat == 0) ? Bq : (mat == 1) ? Bk : Bv;
    uint32_t*       C = (mat == 0) ? Cq : (mat == 1) ? Ck : Cv;
    gemm_core<false, false, false, true>(
        dsm, A, B, (float*)C, nullptr, M, DM, 24, DM,
        blockIdx.y * 128, colt * 128, 0, DM);
}

// ---------------------------------------------------------------------------
// Small TF32 GEMM (tiny action-head output GEMM; plain tf32 B).
// ---------------------------------------------------------------------------
template<int BN, bool BIAS>
__global__ void __launch_bounds__(256)
gemm_small(const uint32_t* __restrict__ A, const uint32_t* __restrict__ B,
           float* __restrict__ C, const float* __restrict__ bias,
           int M, int N, int K, int lda, int ldb, int ldc)
{
    constexpr int NT = (BN / 2) / 8;
    __shared__ uint32_t As[128][20];
    __shared__ uint32_t Bs[BN][20];

    const int tid  = threadIdx.x;
    const int wid  = tid >> 5;
    const int lane = tid & 31;
    const int g    = lane >> 2;
    const int tg   = lane & 3;
    const int warp_m = (wid & 3) * 32;
    const int warp_n = (wid >> 2) * (BN / 2);

    float acc[2][NT][4];
    #pragma unroll
    for (int mt = 0; mt < 2; mt++)
        #pragma unroll
        for (int nt = 0; nt < NT; nt++)
            #pragma unroll
            for (int i = 0; i < 4; i++) acc[mt][nt][i] = 0.f;

    for (int kt = 0; kt < K; kt += 16) {
        #pragma unroll
        for (int i = 0; i < 2; i++) {
            int idx = tid + i * 256;
            int r = idx >> 2, kq = (idx & 3) * 4;
            const uint32_t* ap = A + (long long)r * lda + kt + kq;
            #pragma unroll
            for (int j = 0; j < 4; j++)
                As[r][kq + j] = (r < M && kt + kq + j < K) ? ap[j] : 0u;
        }
        {
            constexpr int ELEMS = BN * 16 / 256;
            #pragma unroll
            for (int i = 0; i < ELEMS; i++) {
                int idx = tid + i * 256;
                int n = idx % BN, k = idx / BN;
                Bs[n][k] = (kt + k < K && n < N) ? B[(long long)(kt + k) * ldb + n] : 0u;
            }
        }
        __syncthreads();

        #pragma unroll
        for (int kk = 0; kk < 16; kk += 8) {
            uint32_t af[2][4];
            #pragma unroll
            for (int mt = 0; mt < 2; mt++) {
                int rs = warp_m + mt * 16 + g;
                af[mt][0] = As[rs][kk + tg];
                af[mt][1] = As[rs + 8][kk + tg];
                af[mt][2] = As[rs][kk + tg + 4];
                af[mt][3] = As[rs + 8][kk + tg + 4];
            }
            uint32_t bf[NT][2];
            #pragma unroll
            for (int nt = 0; nt < NT; nt++) {
                int cs = warp_n + nt * 8 + g;
                bf[nt][0] = Bs[cs][kk + tg];
                bf[nt][1] = Bs[cs][kk + tg + 4];
            }
            #pragma unroll
            for (int mt = 0; mt < 2; mt++)
                #pragma unroll
                for (int nt = 0; nt < NT; nt++)
                    mma_tf32(acc[mt][nt], af[mt], bf[nt]);
        }
        __syncthreads();
    }

    #pragma unroll
    for (int mt = 0; mt < 2; mt++) {
        #pragma unroll
        for (int nt = 0; nt < NT; nt++) {
            int r_base = warp_m + mt * 16 + g;
            int c_base = warp_n + nt * 8 + tg * 2;
            #pragma unroll
            for (int h = 0; h < 2; h++) {
                int r = r_base + h * 8;
                if (r >= M) continue;
                #pragma unroll
                for (int j = 0; j < 2; j++) {
                    int c = c_base + j;
                    if (c >= N) continue;
                    float v = acc[mt][nt][h * 2 + j];
                    if (BIAS) v += bias[c];
                    C[(long long)r * ldc + c] = v;
                }
            }
        }
    }
}

// ---------------------------------------------------------------------------
// Fused flash attention, cp.async double-buffered K/V (V pre-transposed).
// smem: Qs[128*68] K[2][64*68] V[2][64*68] Ps[128*68] + reductions
// ---------------------------------------------------------------------------
#define KVBUF (64 * 68)
#define FLASH_SMEM_WORDS (8704 + 2*KVBUF + 2*KVBUF + 8704 + 256 + 256 + 128 + 128)

__global__ void __launch_bounds__(256)
flash_attn_k(const uint32_t* __restrict__ Qf, const uint32_t* __restrict__ Kf,
             const uint32_t* __restrict__ Vt, uint32_t* __restrict__ ATT)
{
    extern __shared__ uint32_t fsm[];
    uint32_t* Qs   = fsm;                       // [128][68]
    uint32_t* Kb   = Qs + 128 * 68;             // [2][64][68]
    uint32_t* Vb   = Kb + 2 * KVBUF;            // [2][64][68]  (d-major)
    uint32_t* Ps   = Vb + 2 * KVBUF;            // [128][68]
    float* red_m   = (float*)(Ps + 128 * 68);
    float* red_l   = red_m + 256;
    float* row_m   = red_l + 256;
    float* row_l   = row_m + 128;

    const int z  = blockIdx.y;
    const int b  = z / NH, h = z % NH;
    const int q0 = blockIdx.x * 128;

    const int tid  = threadIdx.x;
    const int wid  = tid >> 5;
    const int lane = tid & 31;
    const int g    = lane >> 2;
    const int tg   = lane & 3;
    const int warp_m = (wid & 3) * 32;
    const int warp_n = (wid >> 2) * 32;
    const int colgrp = wid >> 2;

    const uint32_t kbase = smem_u32(Kb);
    const uint32_t vbase = smem_u32(Vb);

    auto prefetch = [&](int buf, int kt0) {
        uint32_t kb = kbase + (uint32_t)buf * KVBUF * 4;
        uint32_t vb = vbase + (uint32_t)buf * KVBUF * 4;
        // K tile: 64 rows (t) x 64 d, row-contiguous
        #pragma unroll
        for (int i = 0; i < 4; i++) {
            int idx = tid + i * 256;
            int kk = idx >> 4, dq = (idx & 15) * 4;
            int t = kt0 + kk;
            const uint32_t* src = Kf + ((long long)(b * SEQ + t)) * DM + h * HS + dq;
            cp16(kb + (uint32_t)(kk * 68 + dq) * 4, src, (t < SEQ) ? 16 : 0);
        }
        // V tile: 64 rows (d) x 64 t, row-contiguous in Vt (pad zeros)
        #pragma unroll
        for (int i = 0; i < 4; i++) {
            int idx = tid + i * 256;
            int d = idx >> 4, tq = (idx & 15) * 4;
            const uint32_t* src = Vt + ((long long)z * HS + d) * SEQT + kt0 + tq;
            cp16(vb + (uint32_t)(d * 68 + tq) * 4, src, 16);
        }
    };

    for (int i = tid; i < 128 * 64; i += 256) {
        int r = i >> 6, d = i & 63;
        int t = q0 + r;
        Qs[r * 68 + d] = (t < SEQ)
            ? Qf[((long long)(b * SEQ + t)) * DM + h * HS + d] : 0u;
    }
    if (tid < 128) { row_m[tid] = -1e30f; row_l[tid] = 0.f; }

    float oacc[2][4][4] = {};

    const int NITER = (SEQ + 63) / 64;   // 7
    prefetch(0, 0);
    cp_commit();
    __syncthreads();

    for (int it = 0; it < NITER; it++) {
        const int cur = it & 1;
        const int kt0 = it * 64;
        const bool more = (it + 1 < NITER);
        if (more) { prefetch(cur ^ 1, kt0 + 64); cp_commit(); }
        if (more) cp_wait1(); else cp_wait0();
        __syncthreads();

        const uint32_t* Ks = Kb + cur * KVBUF;
        const uint32_t* Vs = Vb + cur * KVBUF;

        float sacc[2][4][4] = {};
        #pragma unroll
        for (int ks = 0; ks < 8; ks++) {
            const int kk = ks * 8;
            uint32_t af[2][4];
            #pragma unroll
            for (int mt = 0; mt < 2; mt++) {
                int rs = warp_m + mt * 16 + g;
                af[mt][0] = Qs[rs * 68 + kk + tg];
                af[mt][1] = Qs[(rs + 8) * 68 + kk + tg];
                af[mt][2] = Qs[rs * 68 + kk + tg + 4];
                af[mt][3] = Qs[(rs + 8) * 68 + kk + tg + 4];
            }
            uint32_t bf[4][2];
            #pragma unroll
            for (int nt = 0; nt < 4; nt++) {
                int cs = warp_n + nt * 8 + g;
                bf[nt][0] = Ks[cs * 68 + kk + tg];
                bf[nt][1] = Ks[cs * 68 + kk + tg + 4];
            }
            #pragma unroll
            for (int mt = 0; mt < 2; mt++)
                #pragma unroll
                for (int nt = 0; nt < 4; nt++)
                    mma_tf32(sacc[mt][nt], af[mt], bf[nt]);
        }

        #pragma unroll
        for (int mt = 0; mt < 2; mt++) {
            #pragma unroll
            for (int hh = 0; hh < 2; hh++) {
                float pm = -1e30f;
                #pragma unroll
                for (int nt = 0; nt < 4; nt++) {
                    #pragma unroll
                    for (int j = 0; j < 2; j++) {
                        int kglob = kt0 + warp_n + nt * 8 + tg * 2 + j;
                        float s = (kglob < SEQ) ? sacc[mt][nt][hh * 2 + j] * SCALE : -1e30f;
                        sacc[mt][nt][hh * 2 + j] = s;
                        pm = fmaxf(pm, s);
                    }
                }
                pm = fmaxf(pm, __shfl_xor_sync(0xffffffffu, pm, 1));
                pm = fmaxf(pm, __shfl_xor_sync(0xffffffffu, pm, 2));
                if (tg == 0)
                    red_m[colgrp * 128 + warp_m + mt * 16 + hh * 8 + g] = pm;
            }
        }
        __syncthreads();

        #pragma unroll
        for (int mt = 0; mt < 2; mt++) {
            #pragma unroll
            for (int hh = 0; hh < 2; hh++) {
                int r = warp_m + mt * 16 + hh * 8 + g;
                float mtile = fmaxf(red_m[r], red_m[128 + r]);
                float mnew  = fmaxf(row_m[r], mtile);
                float alpha = __expf(row_m[r] - mnew);
                float psum = 0.f;
                #pragma unroll
                for (int nt = 0; nt < 4; nt++) {
                    #pragma unroll
                    for (int j = 0; j < 2; j++) {
                        float p = __expf(sacc[mt][nt][hh * 2 + j] - mnew);
                        psum += p;
                        Ps[r * 68 + warp_n + nt * 8 + tg * 2 + j] = f2tf32(p);
                        oacc[mt][nt][hh * 2 + j] *= alpha;
                    }
                }
                psum += __shfl_xor_sync(0xffffffffu, psum, 1);
                psum += __shfl_xor_sync(0xffffffffu, psum, 2);
                if (tg == 0) red_l[colgrp * 128 + r] = psum;
            }
        }
        __syncthreads();

        if (tid < 128) {
            int r = tid;
            float mtile = fmaxf(red_m[r], red_m[128 + r]);
            float mold = row_m[r];
            float mnew = fmaxf(mold, mtile);
            row_l[r] = __expf(mold - mnew) * row_l[r] + red_l[r] + red_l[128 + r];
            row_m[r] = mnew;
        }

        #pragma unroll
        for (int ks = 0; ks < 8; ks++) {
            const int kk = ks * 8;
            uint32_t af[2][4];
            #pragma unroll
            for (int mt = 0; mt < 2; mt++) {
                int rs = warp_m + mt * 16 + g;
                af[mt][0] = Ps[rs * 68 + kk + tg];
                af[mt][1] = Ps[(rs + 8) * 68 + kk + tg];
                af[mt][2] = Ps[rs * 68 + kk + tg + 4];
                af[mt][3] = Ps[(rs + 8) * 68 + kk + tg + 4];
            }
            uint32_t bf[4][2];
            #pragma unroll
            for (int nt = 0; nt < 4; nt++) {
                int cs = warp_n + nt * 8 + g;
                bf[nt][0] = Vs[cs * 68 + kk + tg];
                bf[nt][1] = Vs[cs * 68 + kk + tg + 4];
            }
            #pragma unroll
            for (int mt = 0; mt < 2; mt++)
                #pragma unroll
                for (int nt = 0; nt < 4; nt++)
                    mma_tf32(oacc[mt][nt], af[mt], bf[nt]);
        }
        __syncthreads();
    }

    #pragma unroll
    for (int mt = 0; mt < 2; mt++) {
        #pragma unroll
        for (int hh = 0; hh < 2; hh++) {
            int r = warp_m + mt * 16 + hh * 8 + g;
            int t = q0 + r;
            if (t >= SEQ) continue;
            float inv = 1.f / row_l[r];
            #pragma unroll
            for (int nt = 0; nt < 4; nt++) {
                #pragma unroll
                for (int j = 0; j < 2; j++) {
                    int c = warp_n + nt * 8 + tg * 2 + j;
                    ATT[((long long)(b * SEQ + t)) * DM + h * HS + c] =
                        f2tf32(oacc[mt][nt][hh * 2 + j] * inv);
                }
            }
        }
    }
}

// ---------------------------------------------------------------------------
// LayerNorm: fp32 in, tf32-bits out
// ---------------------------------------------------------------------------
__global__ void __launch_bounds__(256)
ln_k(const float* __restrict__ x, uint32_t* __restrict__ out,
     const float* __restrict__ g, const float* __restrict__ b,
     long long strideIn, long long strideOut)
{
    long long r = blockIdx.x;
    const float* xr = x + r * strideIn;
    uint32_t* orow = out + r * strideOut;

    float s = 0.f, s2 = 0.f;
    for (int i = threadIdx.x; i < DM; i += 256) {
        float v = xr[i]; s += v; s2 += v * v;
    }
    for (int o = 16; o; o >>= 1) {
        s  += __shfl_down_sync(0xffffffffu, s,  o);
        s2 += __shfl_down_sync(0xffffffffu, s2, o);
    }
    __shared__ float shs[8], shs2[8];
    int w = threadIdx.x >> 5, ln = threadIdx.x & 31;
    if (ln == 0) { shs[w] = s; shs2[w] = s2; }
    __syncthreads();
    __shared__ float sh_m, sh_inv;
    if (threadIdx.x == 0) {
        float S = 0.f, S2 = 0.f;
        #pragma unroll
        for (int i = 0; i < 8; i++) { S += shs[i]; S2 += shs2[i]; }
        float m = S / (float)DM;
        float var = S2 / (float)DM - m * m;
        sh_m = m; sh_inv = rsqrtf(var + 1e-5f);
    }
    __syncthreads();
    float m = sh_m, inv = sh_inv;
    for (int i = threadIdx.x; i < DM; i += 256)
        orow[i] = f2tf32((xr[i] - m) * inv * g[i] + b[i]);
}

// ---------------------------------------------------------------------------
// Patchify (tf32 out) / scatter / embed
// ---------------------------------------------------------------------------
__global__ void patchify_k(const float* __restrict__ img, uint32_t* __restrict__ P)
{
    int idx = blockIdx.x * blockDim.x + threadIdx.x;
    if (idx >= BATCH * NPATCH * DM) return;
    int d = idx % DM;
    int p = (idx / DM) % NPATCH;
    int b = idx / (DM * NPATCH);
    int c   = d % 3;
    int pix = d / 3;
    int px  = pix % PATCH, py = pix / PATCH;
    int pw  = p % 14,      ph = p / 14;
    int row = ph * PATCH + py, col = pw * PATCH + px;
    P[idx] = f2tf32(img[(((long long)b * IMG + row) * IMG + col) * 3 + c]);
}

__global__ void scatter_patch_k(const float* __restrict__ G, float* __restrict__ X,
                                const float* __restrict__ pb,
                                const float* __restrict__ pos, int tokoff)
{
    int idx = blockIdx.x * blockDim.x + threadIdx.x;
    if (idx >= BATCH * NPATCH * DM) return;
    int d = idx % DM;
    int r = idx / DM;
    int b = r / NPATCH, p = r % NPATCH;
    int t = tokoff + p;
    X[((long long)b * SEQ + t) * DM + d] = G[idx] + pb[d] + pos[(long long)t * DM + d];
}

__global__ void embed_special_k(float* __restrict__ X,
                                const float* __restrict__ cls,
                                const float* __restrict__ goal,
                                const float* __restrict__ tok_emb,
                                const int*   __restrict__ txt,
                                const float* __restrict__ pos)
{
    int idx = blockIdx.x * blockDim.x + threadIdx.x;
    if (idx >= BATCH * 34 * DM) return;
    int d = idx % DM;
    int s = (idx / DM) % 34;
    int b = idx / (DM * 34);
    int t; float v;
    if (s == 0)      { t = 0;   v = cls[d];  }
    else if (s == 1) { t = 197; v = goal[d]; }
    else {
        t = 394 + (s - 2);
        v = tok_emb[(long long)txt[b * TB + (s - 2)] * DM + d];
    }
    X[((long long)b * SEQ + t) * DM + d] = v + pos[(long long)t * DM + d];
}

// ---------------------------------------------------------------------------
// Host driver
// ---------------------------------------------------------------------------
extern "C" void kernel_launch(void* const* d_in, const int* in_sizes, int n_in,
                              void* d_out, int out_size)
{
    (void)in_sizes; (void)n_in; (void)out_size;

    const float* images    = (const float*)d_in[0];
    const float* goal_imgs = (const float*)d_in[1];
    const int*   goals_txt = (const int*)  d_in[2];
    const float* patch_W   = (const float*)d_in[3];
    const float* patch_b   = (const float*)d_in[4];
    const float* tok_emb   = (const float*)d_in[5];
    const float* pos_emb   = (const float*)d_in[6];
    const float* cls_tok   = (const float*)d_in[7];
    const float* goal_tok  = (const float*)d_in[8];
    const float* Wq        = (const float*)d_in[9];
    const float* Wk        = (const float*)d_in[10];
    const float* Wv        = (const float*)d_in[11];
    const float* Wo        = (const float*)d_in[12];
    const float* bo        = (const float*)d_in[13];
    const float* ln1_g     = (const float*)d_in[14];
    const float* ln1_b     = (const float*)d_in[15];
    const float* ln2_g     = (const float*)d_in[16];
    const float* ln2_b     = (const float*)d_in[17];
    const float* W1        = (const float*)d_in[18];
    const float* b1        = (const float*)d_in[19];
    const float* W2        = (const float*)d_in[20];
    const float* b2        = (const float*)d_in[21];
    const float* lnf_g     = (const float*)d_in[22];
    const float* lnf_b     = (const float*)d_in[23];
    const float* ah_W1     = (const float*)d_in[24];
    const float* ah_b1     = (const float*)d_in[25];
    const float* ah_W2     = (const float*)d_in[26];
    const float* ah_b2     = (const float*)d_in[27];
    float* out = (float*)d_out;

    float *X;
    uint32_t *XN, *Qf, *Kf, *Vf, *VT, *ATT, *H, *P, *CLS, *HID, *WT;
    cudaGetSymbolAddress((void**)&X,   g_X);
    cudaGetSymbolAddress((void**)&XN,  g_XN);
    cudaGetSymbolAddress((void**)&Qf,  g_Q);
    cudaGetSymbolAddress((void**)&Kf,  g_K);
    cudaGetSymbolAddress((void**)&Vf,  g_V);
    cudaGetSymbolAddress((void**)&VT,  g_VT);
    cudaGetSymbolAddress((void**)&ATT, g_ATT);
    cudaGetSymbolAddress((void**)&H,   g_H);
    cudaGetSymbolAddress((void**)&P,   g_P);
    cudaGetSymbolAddress((void**)&CLS, g_CLS);
    cudaGetSymbolAddress((void**)&HID, g_HID);
    cudaGetSymbolAddress((void**)&WT,  g_WT);

    const int PTOT  = BATCH * NPATCH * DM;
    const int FSMEM = FLASH_SMEM_WORDS * 4;
    cudaFuncSetAttribute(flash_attn_k, cudaFuncAttributeMaxDynamicSharedMemorySize, FSMEM);
    cudaFuncSetAttribute(gemm_main<false,false,false,false>, cudaFuncAttributeMaxDynamicSharedMemorySize, GSMEM);
    cudaFuncSetAttribute(gemm_main<false,true,true,false>,  cudaFuncAttributeMaxDynamicSharedMemorySize, GSMEM);
    cudaFuncSetAttribute(gemm_main<true,true,false,true>,   cudaFuncAttributeMaxDynamicSharedMemorySize, GSMEM);
    cudaFuncSetAttribute(gemm_qkv,                          cudaFuncAttributeMaxDynamicSharedMemorySize, GSMEM);

    const unsigned MT = (TOK + 127) / 128;  // 107 row tiles

    // --- Weight swizzle (tf32 bits, smem-tile order) ------------------------
    swz_normal_k<<<512,  256>>>(patch_W, WT + OFF_PATCH, DM, DM, 1);
    swz_head_k  <<<2048, 256>>>(Wq, WT + OFF_WQ, NL);
    swz_head_k  <<<2048, 256>>>(Wk, WT + OFF_WK, NL);
    swz_head_k  <<<2048, 256>>>(Wv, WT + OFF_WV, NL);
    swz_normal_k<<<2048, 256>>>(Wo, WT + OFF_WO, DM, DM, NL);
    swz_normal_k<<<4096, 256>>>(W1, WT + OFF_W1, DM, MLPD, NL);
    swz_normal_k<<<4096, 256>>>(W2, WT + OFF_W2, MLPD, DM, NL);
    swz_normal_k<<<2048, 256>>>(ah_W1, WT + OFF_AH1, DM, 4*DM, 1);
    cvt_k       <<<64,   256>>>(ah_W2, WT + OFF_AH2, SZ_AH2);

    // --- Embedding ---------------------------------------------------------
    patchify_k<<<(PTOT + 255) / 256, 256>>>(images, P);
    gemm_main<false,false,false,false><<<dim3(6, (BATCH*NPATCH + 127) / 128, 1), 256, GSMEM>>>(
        P, WT + OFF_PATCH, (float*)H, nullptr, BATCH*NPATCH, DM, 24, DM, DM);
    scatter_patch_k<<<(PTOT + 255) / 256, 256>>>((const float*)H, X, patch_b, pos_emb, 1);

    patchify_k<<<(PTOT + 255) / 256, 256>>>(goal_imgs, P);
    gemm_main<false,false,false,false><<<dim3(6, (BATCH*NPATCH + 127) / 128, 1), 256, GSMEM>>>(
        P, WT + OFF_PATCH, (float*)H, nullptr, BATCH*NPATCH, DM, 24, DM, DM);
    scatter_patch_k<<<(PTOT + 255) / 256, 256>>>((const float*)H, X, patch_b, pos_emb, 198);

    embed_special_k<<<(BATCH*34*DM + 255) / 256, 256>>>(
        X, cls_tok, goal_tok, tok_emb, goals_txt, pos_emb);

    // --- Transformer layers ------------------------------------------------
    for (int l = 0; l < NL; l++) {
        const uint32_t* Wq_l = WT + OFF_WQ + (long long)l * 589824;
        const uint32_t* Wk_l = WT + OFF_WK + (long long)l * 589824;
        const uint32_t* Wv_l = WT + OFF_WV + (long long)l * 589824;
        const uint32_t* Wo_l = WT + OFF_WO + (long long)l * 589824;
        const uint32_t* W1_l = WT + OFF_W1 + (long long)l * 2359296;
        const uint32_t* W2_l = WT + OFF_W2 + (long long)l * 2359296;
        const float* bo_l = bo + (long long)l * DM;
        const float* l1g  = ln1_g + (long long)l * DM;
        const float* l1b  = ln1_b + (long long)l * DM;
        const float* l2g  = ln2_g + (long long)l * DM;
        const float* l2b  = ln2_b + (long long)l * DM;
        const float* b1_l = b1 + (long long)l * MLPD;
        const float* b2_l = b2 + (long long)l * DM;

        ln_k<<<TOK, 256>>>(X, XN, l1g, l1b, DM, DM);

        gemm_qkv<<<dim3(18, MT), 256, GSMEM>>>(XN, Wq_l, Wk_l, Wv_l, Qf, Kf, Vf, TOK);

        vtrans_k<<<dim3(7, BATCH*NH), 256>>>(Vf, VT);

        flash_attn_k<<<dim3(4, BATCH*NH), 256, FSMEM>>>(Qf, Kf, VT, ATT);

        // X += ATT @ Wo + bo  (split-K x3, atomic)
        gemm_main<false,true,true,false><<<dim3(6, MT, 3), 256, GSMEM>>>(
            ATT, Wo_l, X, bo_l, TOK, DM, 24, DM, DM / 3);

        ln_k<<<TOK, 256>>>(X, XN, l2g, l2b, DM, DM);

        // H = relu(XN @ W1 + b1)  (tf32 out)
        gemm_main<true,true,false,true><<<dim3(24, MT, 1), 256, GSMEM>>>(
            XN, W1_l, (float*)H, b1_l, TOK, DM, 24, MLPD, DM);

        // X += H @ W2 + b2  (split-K x4, atomic)
        gemm_main<false,true,true,false><<<dim3(6, MT, 4), 256, GSMEM>>>(
            H, W2_l, X, b2_l, TOK, MLPD, 96, DM, MLPD / 4);
    }

    // --- Final LN (cls rows only) + action head ---------------------------
    ln_k<<<BATCH, 256>>>(X, CLS, lnf_g, lnf_b, (long long)SEQ * DM, DM);

    gemm_main<true,true,false,true><<<dim3(24, 1, 1), 256, GSMEM>>>(
        CLS, WT + OFF_AH1, (float*)HID, ah_b1, BATCH, DM, 24, 4*DM, DM);

    gemm_small<64,true><<<dim3(1, 1, 1), 256>>>(
        HID, WT + OFF_AH2, out, ah_b2, BATCH, AOUT, 4*DM, 4*DM, AOUT, AOUT);
}

// round 17
// speedup vs baseline: 1.0221x; 1.0221x over previous
#include <cuda_runtime.h>
#include <math.h>
#include <stdint.h>

// ---------------------------------------------------------------------------
// Problem constants
// ---------------------------------------------------------------------------
#define BATCH 32
#define IMG   224
#define PATCH 16
#define DM    768
#define NH    12
#define HS    64
#define NL    12
#define TB    32
#define MLPD  3072
#define AOUT  7
#define NPATCH 196
#define SEQ   426
#define TOK   (BATCH*SEQ)   // 13632
#define SCALE 0.03608439182435161f  // 768^-0.5

// ---------------------------------------------------------------------------
// Scratch.  u32 buffers hold tf32-bit values.
// ---------------------------------------------------------------------------
__device__ float    g_X  [TOK*DM];
__device__ uint32_t g_XN [TOK*DM];
__device__ uint32_t g_Q  [TOK*DM];
__device__ uint32_t g_K  [TOK*DM];
__device__ uint32_t g_V  [TOK*DM];
__device__ uint32_t g_ATT[TOK*DM];
__device__ uint32_t g_H  [TOK*MLPD];
__device__ uint32_t g_P  [BATCH*NPATCH*DM];
__device__ uint32_t g_CLS[BATCH*DM];
__device__ uint32_t g_HID[BATCH*4*DM];

// Pre-swizzled weights (tf32 bits, smem-tile order), fixed offsets
#define OFF_PATCH 0LL
#define SZ_PATCH  (589824LL)
#define OFF_WQ    (OFF_PATCH + SZ_PATCH)
#define SZ_WQKV   (12LL*589824)
#define OFF_WK    (OFF_WQ + SZ_WQKV)
#define OFF_WV    (OFF_WK + SZ_WQKV)
#define OFF_WO    (OFF_WV + SZ_WQKV)
#define OFF_W1    (OFF_WO + SZ_WQKV)
#define SZ_WMLP   (12LL*2359296)
#define OFF_W2    (OFF_W1 + SZ_WMLP)
#define OFF_AH1   (OFF_W2 + SZ_WMLP)
#define SZ_AH1    (2359296LL)
#define OFF_AH2   (OFF_AH1 + SZ_AH1)
#define SZ_AH2    (21504LL)
#define WT_TOTAL  (OFF_AH2 + SZ_AH2)
__device__ uint32_t g_WT[WT_TOTAL];

// ---------------------------------------------------------------------------
// Helpers
// ---------------------------------------------------------------------------
__device__ __forceinline__ uint32_t f2tf32(float f) {
    uint32_t r;
    asm("cvt.rna.tf32.f32 %0, %1;" : "=r"(r) : "f"(f));
    return r;
}

__device__ __forceinline__ void mma_tf32(float (&d)[4], const uint32_t (&a)[4],
                                         const uint32_t (&b)[2]) {
    asm volatile(
        "mma.sync.aligned.m16n8k8.row.col.f32.tf32.tf32.f32 "
        "{%0,%1,%2,%3}, {%4,%5,%6,%7}, {%8,%9}, {%0,%1,%2,%3};"
        : "+f"(d[0]), "+f"(d[1]), "+f"(d[2]), "+f"(d[3])
        : "r"(a[0]), "r"(a[1]), "r"(a[2]), "r"(a[3]), "r"(b[0]), "r"(b[1]));
}

__device__ __forceinline__ uint32_t smem_u32(const void* p) {
    uint32_t a;
    asm("{ .reg .u64 t; cvta.to.shared.u64 t, %1; cvt.u32.u64 %0, t; }"
        : "=r"(a) : "l"(p));
    return a;
}

__device__ __forceinline__ void cp16(uint32_t dst, const void* src, int sz) {
    asm volatile("cp.async.cg.shared.global [%0], [%1], 16, %2;"
                 :: "r"(dst), "l"(src), "r"(sz) : "memory");
}
__device__ __forceinline__ void cp_commit() {
    asm volatile("cp.async.commit_group;" ::: "memory");
}
__device__ __forceinline__ void cp_wait1() {
    asm volatile("cp.async.wait_group 1;" ::: "memory");
}
__device__ __forceinline__ void cp_wait0() {
    asm volatile("cp.async.wait_group 0;" ::: "memory");
}

// ---------------------------------------------------------------------------
// Tiled weight swizzle: one 256-thread block produces one dst block
// (128 n x 32 k = 4096 words).  Source reads row-contiguous (coalesced),
// smem [32][129] conflict-free both phases, dst writes linear.
//   HEAD: source is head-packed src[l][h][k][e], n = h*64+e, per-head K*64.
// ---------------------------------------------------------------------------
template<bool HEAD>
__global__ void __launch_bounds__(256)
swz_tile_k(const float* __restrict__ src, uint32_t* __restrict__ dst,
           int K, int N, int nBlocksPerLayer)
{
    __shared__ uint32_t sm[32][129];
    const int kb  = K >> 5;
    const int blk = blockIdx.x;
    const int l   = blk / nBlocksPerLayer;
    const int r   = blk % nBlocksPerLayer;
    const int bn  = r / kb, bk = r % kb;
    const long long per = (long long)K * N;
    const float* s = src + (long long)l * per;
    const int tid = threadIdx.x;

    #pragma unroll
    for (int i = 0; i < 16; i++) {
        int e  = tid + i * 256;
        int kl = e >> 7, nl = e & 127;
        int k  = bk * 32 + kl, n = bn * 128 + nl;
        long long off;
        if (HEAD) off = (long long)(n >> 6) * ((long long)K * 64) +
                        (long long)k * 64 + (n & 63);
        else      off = (long long)k * N + n;
        sm[kl][nl] = f2tf32(s[off]);
    }
    __syncthreads();
    uint32_t* d = dst + (long long)blk * 4096;
    #pragma unroll
    for (int i = 0; i < 16; i++) {
        int inner = tid + i * 256;
        int nl = inner >> 5, kl = inner & 31;
        d[inner] = sm[kl][nl];
    }
}

__global__ void cvt_k(const float* __restrict__ src, uint32_t* __restrict__ dst,
                      long long n)
{
    long long i = (long long)blockIdx.x * blockDim.x + threadIdx.x;
    long long stride = (long long)gridDim.x * blockDim.x;
    for (; i < n; i += stride) dst[i] = f2tf32(src[i]);
}

// ---------------------------------------------------------------------------
// GEMM core: 128x128 tile, BK=32 per phase, cp.async double-buffered.
// ---------------------------------------------------------------------------
#define ABUF (128 * 36)
#define GSMEM (4 * ABUF * 4)

template<bool RELU, bool BIAS, bool ATOMIC, bool OUTTF>
__device__ __forceinline__ void gemm_core(
    uint32_t* dsm,
    const uint32_t* __restrict__ A, const uint32_t* __restrict__ B,
    float* __restrict__ C, const float* __restrict__ bias,
    int M, int lda, int kphases, int ldc,
    int row0, int col0, int kt0, int kend)
{
    const int tid    = threadIdx.x;
    const int wid    = tid >> 5;
    const int lane   = tid & 31;
    const int g      = lane >> 2;
    const int tg     = lane & 3;
    const int warp_m = (wid & 3) * 32;
    const int warp_n = (wid >> 2) * 64;

    float acc[2][8][4];
    #pragma unroll
    for (int mt = 0; mt < 2; mt++)
        #pragma unroll
        for (int nt = 0; nt < 8; nt++)
            #pragma unroll
            for (int i = 0; i < 4; i++) acc[mt][nt][i] = 0.f;

    const uint32_t smem_base = smem_u32(dsm);

    auto prefetch = [&](int buf, int kt) {
        uint32_t abase = smem_base + (uint32_t)buf * ABUF * 4;
        uint32_t bbase = smem_base + (uint32_t)(2 + buf) * ABUF * 4;
        #pragma unroll
        for (int i = 0; i < 4; i++) {
            int idx = tid + i * 256;
            int r   = idx >> 3;
            int kq  = (idx & 7) * 4;
            int gr  = row0 + r;
            const uint32_t* ap = A + (long long)gr * lda + kt + kq;
            cp16(abase + (uint32_t)(r * 36 + kq) * 4, ap, (gr < M) ? 16 : 0);
        }
        const uint32_t* bp = B +
            ((long long)(col0 >> 7) * kphases + (kt >> 5)) * 4096;
        #pragma unroll
        for (int i = 0; i < 4; i++) {
            int idx4 = (tid + i * 256) * 4;
            int n = idx4 >> 5, w = idx4 & 31;
            cp16(bbase + (uint32_t)(n * 36 + w) * 4, bp + idx4, 16);
        }
    };

    const int ntiles = (kend - kt0) >> 5;
    prefetch(0, kt0);
    cp_commit();

    for (int t = 0; t < ntiles; t++) {
        const int cur = t & 1;
        const bool more = (t + 1 < ntiles);
        if (more) { prefetch(cur ^ 1, kt0 + (t + 1) * 32); cp_commit(); }
        if (more) cp_wait1(); else cp_wait0();
        __syncthreads();

        const uint32_t (*As)[36] = (const uint32_t (*)[36])(dsm + cur * ABUF);
        const uint32_t (*Bs)[36] = (const uint32_t (*)[36])(dsm + (2 + cur) * ABUF);

        #pragma unroll
        for (int kk = 0; kk < 32; kk += 8) {
            uint32_t af[2][4];
            #pragma unroll
            for (int mt = 0; mt < 2; mt++) {
                int rs = warp_m + mt * 16 + g;
                af[mt][0] = As[rs][kk + tg];
                af[mt][1] = As[rs + 8][kk + tg];
                af[mt][2] = As[rs][kk + tg + 4];
                af[mt][3] = As[rs + 8][kk + tg + 4];
            }
            uint32_t bf[8][2];
            #pragma unroll
            for (int nt = 0; nt < 8; nt++) {
                int cs = warp_n + nt * 8 + g;
                bf[nt][0] = Bs[cs][kk + tg];
                bf[nt][1] = Bs[cs][kk + tg + 4];
            }
            #pragma unroll
            for (int mt = 0; mt < 2; mt++)
                #pragma unroll
                for (int nt = 0; nt < 8; nt++)
                    mma_tf32(acc[mt][nt], af[mt], bf[nt]);
        }
        __syncthreads();
    }

    #pragma unroll
    for (int mt = 0; mt < 2; mt++) {
        #pragma unroll
        for (int nt = 0; nt < 8; nt++) {
            int r_base = row0 + warp_m + mt * 16 + g;
            int c_base = col0 + warp_n + nt * 8 + tg * 2;
            #pragma unroll
            for (int h = 0; h < 2; h++) {
                int r = r_base + h * 8;
                if (r >= M) continue;
                #pragma unroll
                for (int j = 0; j < 2; j++) {
                    int c = c_base + j;
                    float v = acc[mt][nt][h * 2 + j];
                    long long ci = (long long)r * ldc + c;
                    if (ATOMIC) {
                        if (BIAS && blockIdx.z == 0) v += bias[c];
                        atomicAdd(&C[ci], v);
                    } else {
                        if (BIAS) v += bias[c];
                        if (RELU) v = fmaxf(v, 0.f);
                        if (OUTTF) ((uint32_t*)C)[ci] = f2tf32(v);
                        else       C[ci] = v;
                    }
                }
            }
        }
    }
}

template<bool RELU, bool BIAS, bool ATOMIC, bool OUTTF>
__global__ void __launch_bounds__(256, 2)
gemm_main(const uint32_t* __restrict__ A, const uint32_t* __restrict__ B,
          float* __restrict__ C, const float* __restrict__ bias,
          int M, int lda, int kphases, int ldc, int ksz)
{
    extern __shared__ uint32_t dsm[];
    int kt0 = blockIdx.z * ksz;
    gemm_core<RELU, BIAS, ATOMIC, OUTTF>(
        dsm, A, B, C, bias, M, lda, kphases, ldc,
        blockIdx.y * 128, blockIdx.x * 128, kt0, kt0 + ksz);
}

__global__ void __launch_bounds__(256, 2)
gemm_qkv(const uint32_t* __restrict__ A,
         const uint32_t* __restrict__ Bq, const uint32_t* __restrict__ Bk,
         const uint32_t* __restrict__ Bv,
         uint32_t* __restrict__ Cq, uint32_t* __restrict__ Ck,
         uint32_t* __restrict__ Cv, int M)
{
    extern __shared__ uint32_t dsm[];
    const int mat  = blockIdx.x / 6;
    const int colt = blockIdx.x % 6;
    const uint32_t* B = (mat == 0) ? Bq : (mat == 1) ? Bk : Bv;
    uint32_t*       C = (mat == 0) ? Cq : (mat == 1) ? Ck : Cv;
    gemm_core<false, false, false, true>(
        dsm, A, B, (float*)C, nullptr, M, DM, 24, DM,
        blockIdx.y * 128, colt * 128, 0, DM);
}

// ---------------------------------------------------------------------------
// Small TF32 GEMM (tiny action-head output GEMM; plain tf32 B).
// ---------------------------------------------------------------------------
template<int BN, bool BIAS>
__global__ void __launch_bounds__(256)
gemm_small(const uint32_t* __restrict__ A, const uint32_t* __restrict__ B,
           float* __restrict__ C, const float* __restrict__ bias,
           int M, int N, int K, int lda, int ldb, int ldc)
{
    constexpr int NT = (BN / 2) / 8;
    __shared__ uint32_t As[128][20];
    __shared__ uint32_t Bs[BN][20];

    const int tid  = threadIdx.x;
    const int wid  = tid >> 5;
    const int lane = tid & 31;
    const int g    = lane >> 2;
    const int tg   = lane & 3;
    const int warp_m = (wid & 3) * 32;
    const int warp_n = (wid >> 2) * (BN / 2);

    float acc[2][NT][4];
    #pragma unroll
    for (int mt = 0; mt < 2; mt++)
        #pragma unroll
        for (int nt = 0; nt < NT; nt++)
            #pragma unroll
            for (int i = 0; i < 4; i++) acc[mt][nt][i] = 0.f;

    for (int kt = 0; kt < K; kt += 16) {
        #pragma unroll
        for (int i = 0; i < 2; i++) {
            int idx = tid + i * 256;
            int r = idx >> 2, kq = (idx & 3) * 4;
            const uint32_t* ap = A + (long long)r * lda + kt + kq;
            #pragma unroll
            for (int j = 0; j < 4; j++)
                As[r][kq + j] = (r < M && kt + kq + j < K) ? ap[j] : 0u;
        }
        {
            constexpr int ELEMS = BN * 16 / 256;
            #pragma unroll
            for (int i = 0; i < ELEMS; i++) {
                int idx = tid + i * 256;
                int n = idx % BN, k = idx / BN;
                Bs[n][k] = (kt + k < K && n < N) ? B[(long long)(kt + k) * ldb + n] : 0u;
            }
        }
        __syncthreads();

        #pragma unroll
        for (int kk = 0; kk < 16; kk += 8) {
            uint32_t af[2][4];
            #pragma unroll
            for (int mt = 0; mt < 2; mt++) {
                int rs = warp_m + mt * 16 + g;
                af[mt][0] = As[rs][kk + tg];
                af[mt][1] = As[rs + 8][kk + tg];
                af[mt][2] = As[rs][kk + tg + 4];
                af[mt][3] = As[rs + 8][kk + tg + 4];
            }
            uint32_t bf[NT][2];
            #pragma unroll
            for (int nt = 0; nt < NT; nt++) {
                int cs = warp_n + nt * 8 + g;
                bf[nt][0] = Bs[cs][kk + tg];
                bf[nt][1] = Bs[cs][kk + tg + 4];
            }
            #pragma unroll
            for (int mt = 0; mt < 2; mt++)
                #pragma unroll
                for (int nt = 0; nt < NT; nt++)
                    mma_tf32(acc[mt][nt], af[mt], bf[nt]);
        }
        __syncthreads();
    }

    #pragma unroll
    for (int mt = 0; mt < 2; mt++) {
        #pragma unroll
        for (int nt = 0; nt < NT; nt++) {
            int r_base = warp_m + mt * 16 + g;
            int c_base = warp_n + nt * 8 + tg * 2;
            #pragma unroll
            for (int h = 0; h < 2; h++) {
                int r = r_base + h * 8;
                if (r >= M) continue;
                #pragma unroll
                for (int j = 0; j < 2; j++) {
                    int c = c_base + j;
                    if (c >= N) continue;
                    float v = acc[mt][nt][h * 2 + j];
                    if (BIAS) v += bias[c];
                    C[(long long)r * ldc + c] = v;
                }
            }
        }
    }
}

// ---------------------------------------------------------------------------
// Fused flash attention (R15 version — proven best).
// ---------------------------------------------------------------------------
#define FLASH_SMEM_WORDS (8704 + 4352 + 4352 + 8704 + 256 + 256 + 128 + 128)

__global__ void __launch_bounds__(256)
flash_attn_k(const uint32_t* __restrict__ Qf, const uint32_t* __restrict__ Kf,
             const uint32_t* __restrict__ Vf, uint32_t* __restrict__ ATT)
{
    extern __shared__ uint32_t fsm[];
    uint32_t* Qs   = fsm;
    uint32_t* Ks   = Qs + 128 * 68;
    uint32_t* Vs   = Ks + 64 * 68;
    uint32_t* Ps   = Vs + 64 * 68;
    float* red_m   = (float*)(Ps + 128 * 68);
    float* red_l   = red_m + 256;
    float* row_m   = red_l + 256;
    float* row_l   = row_m + 128;

    const int z  = blockIdx.y;
    const int b  = z / NH, h = z % NH;
    const int q0 = blockIdx.x * 128;

    const int tid  = threadIdx.x;
    const int wid  = tid >> 5;
    const int lane = tid & 31;
    const int g    = lane >> 2;
    const int tg   = lane & 3;
    const int warp_m = (wid & 3) * 32;
    const int warp_n = (wid >> 2) * 32;
    const int colgrp = wid >> 2;

    for (int i = tid; i < 128 * 64; i += 256) {
        int r = i >> 6, d = i & 63;
        int t = q0 + r;
        Qs[r * 68 + d] = (t < SEQ)
            ? Qf[((long long)(b * SEQ + t)) * DM + h * HS + d] : 0u;
    }
    if (tid < 128) { row_m[tid] = -1e30f; row_l[tid] = 0.f; }

    float oacc[2][4][4] = {};
    __syncthreads();

    for (int kt0 = 0; kt0 < SEQ; kt0 += 64) {
        for (int i = tid; i < 64 * 64; i += 256) {
            int kk = i >> 6, d = i & 63;
            int t = kt0 + kk;
            uint32_t kv = 0u, vv = 0u;
            if (t < SEQ) {
                long long base = ((long long)(b * SEQ + t)) * DM + h * HS + d;
                kv = Kf[base];
                vv = Vf[base];
            }
            Ks[kk * 68 + d] = kv;
            Vs[d * 68 + kk] = vv;
        }
        __syncthreads();

        float sacc[2][4][4] = {};
        #pragma unroll
        for (int ks = 0; ks < 8; ks++) {
            const int kk = ks * 8;
            uint32_t af[2][4];
            #pragma unroll
            for (int mt = 0; mt < 2; mt++) {
                int rs = warp_m + mt * 16 + g;
                af[mt][0] = Qs[rs * 68 + kk + tg];
                af[mt][1] = Qs[(rs + 8) * 68 + kk + tg];
                af[mt][2] = Qs[rs * 68 + kk + tg + 4];
                af[mt][3] = Qs[(rs + 8) * 68 + kk + tg + 4];
            }
            uint32_t bf[4][2];
            #pragma unroll
            for (int nt = 0; nt < 4; nt++) {
                int cs = warp_n + nt * 8 + g;
                bf[nt][0] = Ks[cs * 68 + kk + tg];
                bf[nt][1] = Ks[cs * 68 + kk + tg + 4];
            }
            #pragma unroll
            for (int mt = 0; mt < 2; mt++)
                #pragma unroll
                for (int nt = 0; nt < 4; nt++)
                    mma_tf32(sacc[mt][nt], af[mt], bf[nt]);
        }

        #pragma unroll
        for (int mt = 0; mt < 2; mt++) {
            #pragma unroll
            for (int hh = 0; hh < 2; hh++) {
                float pm = -1e30f;
                #pragma unroll
                for (int nt = 0; nt < 4; nt++) {
                    #pragma unroll
                    for (int j = 0; j < 2; j++) {
                        int kglob = kt0 + warp_n + nt * 8 + tg * 2 + j;
                        float s = (kglob < SEQ) ? sacc[mt][nt][hh * 2 + j] * SCALE : -1e30f;
                        sacc[mt][nt][hh * 2 + j] = s;
                        pm = fmaxf(pm, s);
                    }
                }
                pm = fmaxf(pm, __shfl_xor_sync(0xffffffffu, pm, 1));
                pm = fmaxf(pm, __shfl_xor_sync(0xffffffffu, pm, 2));
                if (tg == 0)
                    red_m[colgrp * 128 + warp_m + mt * 16 + hh * 8 + g] = pm;
            }
        }
        __syncthreads();

        #pragma unroll
        for (int mt = 0; mt < 2; mt++) {
            #pragma unroll
            for (int hh = 0; hh < 2; hh++) {
                int r = warp_m + mt * 16 + hh * 8 + g;
                float mtile = fmaxf(red_m[r], red_m[128 + r]);
                float mnew  = fmaxf(row_m[r], mtile);
                float alpha = __expf(row_m[r] - mnew);
                float psum = 0.f;
                #pragma unroll
                for (int nt = 0; nt < 4; nt++) {
                    #pragma unroll
                    for (int j = 0; j < 2; j++) {
                        float p = __expf(sacc[mt][nt][hh * 2 + j] - mnew);
                        psum += p;
                        Ps[r * 68 + warp_n + nt * 8 + tg * 2 + j] = f2tf32(p);
                        oacc[mt][nt][hh * 2 + j] *= alpha;
                    }
                }
                psum += __shfl_xor_sync(0xffffffffu, psum, 1);
                psum += __shfl_xor_sync(0xffffffffu, psum, 2);
                if (tg == 0) red_l[colgrp * 128 + r] = psum;
            }
        }
        __syncthreads();

        if (tid < 128) {
            int r = tid;
            float mtile = fmaxf(red_m[r], red_m[128 + r]);
            float mold = row_m[r];
            float mnew = fmaxf(mold, mtile);
            row_l[r] = __expf(mold - mnew) * row_l[r] + red_l[r] + red_l[128 + r];
            row_m[r] = mnew;
        }

        #pragma unroll
        for (int ks = 0; ks < 8; ks++) {
            const int kk = ks * 8;
            uint32_t af[2][4];
            #pragma unroll
            for (int mt = 0; mt < 2; mt++) {
                int rs = warp_m + mt * 16 + g;
                af[mt][0] = Ps[rs * 68 + kk + tg];
                af[mt][1] = Ps[(rs + 8) * 68 + kk + tg];
                af[mt][2] = Ps[rs * 68 + kk + tg + 4];
                af[mt][3] = Ps[(rs + 8) * 68 + kk + tg + 4];
            }
            uint32_t bf[4][2];
            #pragma unroll
            for (int nt = 0; nt < 4; nt++) {
                int cs = warp_n + nt * 8 + g;
                bf[nt][0] = Vs[cs * 68 + kk + tg];
                bf[nt][1] = Vs[cs * 68 + kk + tg + 4];
            }
            #pragma unroll
            for (int mt = 0; mt < 2; mt++)
                #pragma unroll
                for (int nt = 0; nt < 4; nt++)
                    mma_tf32(oacc[mt][nt], af[mt], bf[nt]);
        }
        __syncthreads();
    }

    #pragma unroll
    for (int mt = 0; mt < 2; mt++) {
        #pragma unroll
        for (int hh = 0; hh < 2; hh++) {
            int r = warp_m + mt * 16 + hh * 8 + g;
            int t = q0 + r;
            if (t >= SEQ) continue;
            float inv = 1.f / row_l[r];
            #pragma unroll
            for (int nt = 0; nt < 4; nt++) {
                #pragma unroll
                for (int j = 0; j < 2; j++) {
                    int c = warp_n + nt * 8 + tg * 2 + j;
                    ATT[((long long)(b * SEQ + t)) * DM + h * HS + c] =
                        f2tf32(oacc[mt][nt][hh * 2 + j] * inv);
                }
            }
        }
    }
}

// ---------------------------------------------------------------------------
// LayerNorm: fp32 in, tf32-bits out
// ---------------------------------------------------------------------------
__global__ void __launch_bounds__(256)
ln_k(const float* __restrict__ x, uint32_t* __restrict__ out,
     const float* __restrict__ g, const float* __restrict__ b,
     long long strideIn, long long strideOut)
{
    long long r = blockIdx.x;
    const float* xr = x + r * strideIn;
    uint32_t* orow = out + r * strideOut;

    float s = 0.f, s2 = 0.f;
    for (int i = threadIdx.x; i < DM; i += 256) {
        float v = xr[i]; s += v; s2 += v * v;
    }
    for (int o = 16; o; o >>= 1) {
        s  += __shfl_down_sync(0xffffffffu, s,  o);
        s2 += __shfl_down_sync(0xffffffffu, s2, o);
    }
    __shared__ float shs[8], shs2[8];
    int w = threadIdx.x >> 5, ln = threadIdx.x & 31;
    if (ln == 0) { shs[w] = s; shs2[w] = s2; }
    __syncthreads();
    __shared__ float sh_m, sh_inv;
    if (threadIdx.x == 0) {
        float S = 0.f, S2 = 0.f;
        #pragma unroll
        for (int i = 0; i < 8; i++) { S += shs[i]; S2 += shs2[i]; }
        float m = S / (float)DM;
        float var = S2 / (float)DM - m * m;
        sh_m = m; sh_inv = rsqrtf(var + 1e-5f);
    }
    __syncthreads();
    float m = sh_m, inv = sh_inv;
    for (int i = threadIdx.x; i < DM; i += 256)
        orow[i] = f2tf32((xr[i] - m) * inv * g[i] + b[i]);
}

// ---------------------------------------------------------------------------
// Patchify (tf32 out) / scatter / embed
// ---------------------------------------------------------------------------
__global__ void patchify_k(const float* __restrict__ img, uint32_t* __restrict__ P)
{
    int idx = blockIdx.x * blockDim.x + threadIdx.x;
    if (idx >= BATCH * NPATCH * DM) return;
    int d = idx % DM;
    int p = (idx / DM) % NPATCH;
    int b = idx / (DM * NPATCH);
    int c   = d % 3;
    int pix = d / 3;
    int px  = pix % PATCH, py = pix / PATCH;
    int pw  = p % 14,      ph = p / 14;
    int row = ph * PATCH + py, col = pw * PATCH + px;
    P[idx] = f2tf32(img[(((long long)b * IMG + row) * IMG + col) * 3 + c]);
}

__global__ void scatter_patch_k(const float* __restrict__ G, float* __restrict__ X,
                                const float* __restrict__ pb,
                                const float* __restrict__ pos, int tokoff)
{
    int idx = blockIdx.x * blockDim.x + threadIdx.x;
    if (idx >= BATCH * NPATCH * DM) return;
    int d = idx % DM;
    int r = idx / DM;
    int b = r / NPATCH, p = r % NPATCH;
    int t = tokoff + p;
    X[((long long)b * SEQ + t) * DM + d] = G[idx] + pb[d] + pos[(long long)t * DM + d];
}

__global__ void embed_special_k(float* __restrict__ X,
                                const float* __restrict__ cls,
                                const float* __restrict__ goal,
                                const float* __restrict__ tok_emb,
                                const int*   __restrict__ txt,
                                const float* __restrict__ pos)
{
    int idx = blockIdx.x * blockDim.x + threadIdx.x;
    if (idx >= BATCH * 34 * DM) return;
    int d = idx % DM;
    int s = (idx / DM) % 34;
    int b = idx / (DM * 34);
    int t; float v;
    if (s == 0)      { t = 0;   v = cls[d];  }
    else if (s == 1) { t = 197; v = goal[d]; }
    else {
        t = 394 + (s - 2);
        v = tok_emb[(long long)txt[b * TB + (s - 2)] * DM + d];
    }
    X[((long long)b * SEQ + t) * DM + d] = v + pos[(long long)t * DM + d];
}

// ---------------------------------------------------------------------------
// Host driver
// ---------------------------------------------------------------------------
extern "C" void kernel_launch(void* const* d_in, const int* in_sizes, int n_in,
                              void* d_out, int out_size)
{
    (void)in_sizes; (void)n_in; (void)out_size;

    const float* images    = (const float*)d_in[0];
    const float* goal_imgs = (const float*)d_in[1];
    const int*   goals_txt = (const int*)  d_in[2];
    const float* patch_W   = (const float*)d_in[3];
    const float* patch_b   = (const float*)d_in[4];
    const float* tok_emb   = (const float*)d_in[5];
    const float* pos_emb   = (const float*)d_in[6];
    const float* cls_tok   = (const float*)d_in[7];
    const float* goal_tok  = (const float*)d_in[8];
    const float* Wq        = (const float*)d_in[9];
    const float* Wk        = (const float*)d_in[10];
    const float* Wv        = (const float*)d_in[11];
    const float* Wo        = (const float*)d_in[12];
    const float* bo        = (const float*)d_in[13];
    const float* ln1_g     = (const float*)d_in[14];
    const float* ln1_b     = (const float*)d_in[15];
    const float* ln2_g     = (const float*)d_in[16];
    const float* ln2_b     = (const float*)d_in[17];
    const float* W1        = (const float*)d_in[18];
    const float* b1        = (const float*)d_in[19];
    const float* W2        = (const float*)d_in[20];
    const float* b2        = (const float*)d_in[21];
    const float* lnf_g     = (const float*)d_in[22];
    const float* lnf_b     = (const float*)d_in[23];
    const float* ah_W1     = (const float*)d_in[24];
    const float* ah_b1     = (const float*)d_in[25];
    const float* ah_W2     = (const float*)d_in[26];
    const float* ah_b2     = (const float*)d_in[27];
    float* out = (float*)d_out;

    float *X;
    uint32_t *XN, *Qf, *Kf, *Vf, *ATT, *H, *P, *CLS, *HID, *WT;
    cudaGetSymbolAddress((void**)&X,   g_X);
    cudaGetSymbolAddress((void**)&XN,  g_XN);
    cudaGetSymbolAddress((void**)&Qf,  g_Q);
    cudaGetSymbolAddress((void**)&Kf,  g_K);
    cudaGetSymbolAddress((void**)&Vf,  g_V);
    cudaGetSymbolAddress((void**)&ATT, g_ATT);
    cudaGetSymbolAddress((void**)&H,   g_H);
    cudaGetSymbolAddress((void**)&P,   g_P);
    cudaGetSymbolAddress((void**)&CLS, g_CLS);
    cudaGetSymbolAddress((void**)&HID, g_HID);
    cudaGetSymbolAddress((void**)&WT,  g_WT);

    const int PTOT  = BATCH * NPATCH * DM;
    const int FSMEM = FLASH_SMEM_WORDS * 4;
    cudaFuncSetAttribute(flash_attn_k, cudaFuncAttributeMaxDynamicSharedMemorySize, FSMEM);
    cudaFuncSetAttribute(gemm_main<false,false,false,false>, cudaFuncAttributeMaxDynamicSharedMemorySize, GSMEM);
    cudaFuncSetAttribute(gemm_main<false,true,true,false>,  cudaFuncAttributeMaxDynamicSharedMemorySize, GSMEM);
    cudaFuncSetAttribute(gemm_main<true,true,false,true>,   cudaFuncAttributeMaxDynamicSharedMemorySize, GSMEM);
    cudaFuncSetAttribute(gemm_qkv,                          cudaFuncAttributeMaxDynamicSharedMemorySize, GSMEM);

    const unsigned MT = (TOK + 127) / 128;  // 107 row tiles

    // --- Weight swizzle (tiled, coalesced both sides) -----------------------
    // blocks per layer: (N/128)*(K/32)
    swz_tile_k<false><<<6 * 24, 256>>>(patch_W, WT + OFF_PATCH, DM, DM, 6 * 24);
    swz_tile_k<true ><<<NL * 6 * 24, 256>>>(Wq, WT + OFF_WQ, DM, DM, 6 * 24);
    swz_tile_k<true ><<<NL * 6 * 24, 256>>>(Wk, WT + OFF_WK, DM, DM, 6 * 24);
    swz_tile_k<true ><<<NL * 6 * 24, 256>>>(Wv, WT + OFF_WV, DM, DM, 6 * 24);
    swz_tile_k<false><<<NL * 6 * 24, 256>>>(Wo, WT + OFF_WO, DM, DM, 6 * 24);
    swz_tile_k<false><<<NL * 24 * 24, 256>>>(W1, WT + OFF_W1, DM, MLPD, 24 * 24);
    swz_tile_k<false><<<NL * 6 * 96, 256>>>(W2, WT + OFF_W2, MLPD, DM, 6 * 96);
    swz_tile_k<false><<<24 * 24, 256>>>(ah_W1, WT + OFF_AH1, DM, 4 * DM, 24 * 24);
    cvt_k<<<64, 256>>>(ah_W2, WT + OFF_AH2, SZ_AH2);

    // --- Embedding ---------------------------------------------------------
    patchify_k<<<(PTOT + 255) / 256, 256>>>(images, P);
    gemm_main<false,false,false,false><<<dim3(6, (BATCH*NPATCH + 127) / 128, 1), 256, GSMEM>>>(
        P, WT + OFF_PATCH, (float*)H, nullptr, BATCH*NPATCH, DM, 24, DM, DM);
    scatter_patch_k<<<(PTOT + 255) / 256, 256>>>((const float*)H, X, patch_b, pos_emb, 1);

    patchify_k<<<(PTOT + 255) / 256, 256>>>(goal_imgs, P);
    gemm_main<false,false,false,false><<<dim3(6, (BATCH*NPATCH + 127) / 128, 1), 256, GSMEM>>>(
        P, WT + OFF_PATCH, (float*)H, nullptr, BATCH*NPATCH, DM, 24, DM, DM);
    scatter_patch_k<<<(PTOT + 255) / 256, 256>>>((const float*)H, X, patch_b, pos_emb, 198);

    embed_special_k<<<(BATCH*34*DM + 255) / 256, 256>>>(
        X, cls_tok, goal_tok, tok_emb, goals_txt, pos_emb);

    // --- Transformer layers ------------------------------------------------
    for (int l = 0; l < NL; l++) {
        const uint32_t* Wq_l = WT + OFF_WQ + (long long)l * 589824;
        const uint32_t* Wk_l = WT + OFF_WK + (long long)l * 589824;
        const uint32_t* Wv_l = WT + OFF_WV + (long long)l * 589824;
        const uint32_t* Wo_l = WT + OFF_WO + (long long)l * 589824;
        const uint32_t* W1_l = WT + OFF_W1 + (long long)l * 2359296;
        const uint32_t* W2_l = WT + OFF_W2 + (long long)l * 2359296;
        const float* bo_l = bo + (long long)l * DM;
        const float* l1g  = ln1_g + (long long)l * DM;
        const float* l1b  = ln1_b + (long long)l * DM;
        const float* l2g  = ln2_g + (long long)l * DM;
        const float* l2b  = ln2_b + (long long)l * DM;
        const float* b1_l = b1 + (long long)l * MLPD;
        const float* b2_l = b2 + (long long)l * DM;

        ln_k<<<TOK, 256>>>(X, XN, l1g, l1b, DM, DM);

        gemm_qkv<<<dim3(18, MT), 256, GSMEM>>>(XN, Wq_l, Wk_l, Wv_l, Qf, Kf, Vf, TOK);

        flash_attn_k<<<dim3(4, BATCH*NH), 256, FSMEM>>>(Qf, Kf, Vf, ATT);

        // X += ATT @ Wo + bo  (split-K x3, atomic)
        gemm_main<false,true,true,false><<<dim3(6, MT, 3), 256, GSMEM>>>(
            ATT, Wo_l, X, bo_l, TOK, DM, 24, DM, DM / 3);

        ln_k<<<TOK, 256>>>(X, XN, l2g, l2b, DM, DM);

        // H = relu(XN @ W1 + b1)  (tf32 out)
        gemm_main<true,true,false,true><<<dim3(24, MT, 1), 256, GSMEM>>>(
            XN, W1_l, (float*)H, b1_l, TOK, DM, 24, MLPD, DM);

        // X += H @ W2 + b2  (split-K x4, atomic)
        gemm_main<false,true,true,false><<<dim3(6, MT, 4), 256, GSMEM>>>(
            H, W2_l, X, b2_l, TOK, MLPD, 96, DM, MLPD / 4);
    }

    // --- Final LN (cls rows only) + action head ---------------------------
    ln_k<<<BATCH, 256>>>(X, CLS, lnf_g, lnf_b, (long long)SEQ * DM, DM);

    gemm_main<true,true,false,true><<<dim3(24, 1, 1), 256, GSMEM>>>(
        CLS, WT + OFF_AH1, (float*)HID, ah_b1, BATCH, DM, 24, 4*DM, DM);

    gemm_small<64,true><<<dim3(1, 1, 1), 256>>>(
        HID, WT + OFF_AH2, out, ah_b2, BATCH, AOUT, 4*DM, 4*DM, AOUT, AOUT);
}